// round 1
// baseline (speedup 1.0000x reference)
#include <cuda_runtime.h>

#define BS    16
#define CCH   256
#define NPIX  16384
#define TOPK  12
#define TPB   256

// Device-global scratch (no allocations allowed in kernel_launch)
__device__ signed char g_mask[BS * NPIX];     // bit0 = fg mask, bit1 = bg mask
__device__ float       g_pf[BS * NPIX];       // pred_fg
__device__ float       g_pb[BS * NPIX];       // pred_bg
__device__ int         g_cnt[2 * BS];         // [0..15] fg counts, [16..31] bg counts
__device__ int         g_idx[2 * BS * TOPK];  // fg top-12 indices, then bg top-12

// Block-cooperative top-K (K=12) with lowest-index tie-break (matches jax.lax.top_k).
__device__ __forceinline__ void topk_select(const float* __restrict__ arr,
                                            int* ch_sh, float* sv, int* si,
                                            int* out_idx) {
    int t = threadIdx.x;
    for (int k = 0; k < TOPK; k++) {
        float best = -3.402823466e38f;
        int   bidx = NPIX;
        for (int i = t; i < NPIX; i += TPB) {
            bool excl = false;
            #pragma unroll
            for (int j = 0; j < TOPK; j++)
                if (j < k) excl |= (i == ch_sh[j]);
            if (!excl) {
                float v = arr[i];
                // strictly-greater keeps lowest index within a thread's ascending stride
                if (v > best) { best = v; bidx = i; }
            }
        }
        sv[t] = best; si[t] = bidx;
        __syncthreads();
        for (int off = TPB / 2; off > 0; off >>= 1) {
            if (t < off) {
                float v2 = sv[t + off]; int i2 = si[t + off];
                if (v2 > sv[t] || (v2 == sv[t] && i2 < si[t])) { sv[t] = v2; si[t] = i2; }
            }
            __syncthreads();
        }
        if (t == 0) ch_sh[k] = si[0];
        __syncthreads();
    }
    if (t < TOPK) out_idx[t] = ch_sh[t];
}

// Phase A: softmax probs, masks, counts, top-12 indices. One block per batch.
__global__ void ssp_phaseA(const float* __restrict__ logits,
                           const float* __restrict__ tau_p) {
    int b = blockIdx.x, t = threadIdx.x;
    __shared__ int   s_cf, s_cb;
    __shared__ float sv[TPB];
    __shared__ int   si[TPB];
    __shared__ int   ch[TOPK];
    if (t == 0) { s_cf = 0; s_cb = 0; }
    __syncthreads();

    float tau = tau_p[0];
    float tf  = 1.0f / (1.0f + expf(-tau));   // fg_thres = sigmoid(tau)
    float tb  = 1.0f - tf;                    // bg_thres

    const float* o0 = logits + (size_t)b * 2 * NPIX;       // channel 0 (bg logit)
    const float* o1 = o0 + NPIX;                           // channel 1 (fg logit)

    int lf = 0, lb = 0;
    for (int i = t; i < NPIX; i += TPB) {
        float a0 = o0[i], a1 = o1[i];
        float m  = fmaxf(a0, a1);
        float e0 = expf(a0 - m), e1 = expf(a1 - m);
        float den = e0 + e1;
        float pf = e1 / den;   // pred_fg
        float pb = e0 / den;   // pred_bg (not exactly 1-pf in fp32; match reference)
        g_pf[b * NPIX + i] = pf;
        g_pb[b * NPIX + i] = pb;
        int s = 0;
        if (pf > tf) { s |= 1; lf++; }
        if (pb > tb) { s |= 2; lb++; }
        g_mask[b * NPIX + i] = (signed char)s;
    }
    atomicAdd(&s_cf, lf);
    atomicAdd(&s_cb, lb);
    __syncthreads();
    if (t == 0) { g_cnt[b] = s_cf; g_cnt[BS + b] = s_cb; }
    __syncthreads();   // g_pf/g_pb writes visible block-wide

    topk_select(g_pf + (size_t)b * NPIX, ch, sv, si, &g_idx[b * TOPK]);
    __syncthreads();
    topk_select(g_pb + (size_t)b * NPIX, ch, sv, si, &g_idx[(BS + b) * TOPK]);
}

// Phase B: streaming masked reduction over feature_q + fused top-k gather + select.
// One block per (b, c) row of 16384 floats.
__global__ void ssp_phaseB(const float* __restrict__ feat,
                           float* __restrict__ res) {
    int c = blockIdx.x, b = blockIdx.y, t = threadIdx.x;
    size_t rowoff = ((size_t)b * CCH + c) * (size_t)NPIX;
    const float4* row = (const float4*)(feat + rowoff);
    const char4*  sp  = (const char4*)(g_mask + (size_t)b * NPIX);

    float sf = 0.0f, sb = 0.0f;
    #pragma unroll
    for (int it = 0; it < NPIX / 4 / TPB; ++it) {   // 16 iters of LDG.128
        int i = t + it * TPB;
        float4 v = row[i];
        char4  m = sp[i];
        sf += (m.x & 1) ? v.x : 0.0f;  sb += (m.x & 2) ? v.x : 0.0f;
        sf += (m.y & 1) ? v.y : 0.0f;  sb += (m.y & 2) ? v.y : 0.0f;
        sf += (m.z & 1) ? v.z : 0.0f;  sb += (m.z & 2) ? v.z : 0.0f;
        sf += (m.w & 1) ? v.w : 0.0f;  sb += (m.w & 2) ? v.w : 0.0f;
    }
    // warp reduce
    #pragma unroll
    for (int off = 16; off; off >>= 1) {
        sf += __shfl_down_sync(0xffffffffu, sf, off);
        sb += __shfl_down_sync(0xffffffffu, sb, off);
    }
    __shared__ float wsf[8], wsb[8];
    __shared__ float tkv[2 * TOPK];
    if ((t & 31) == 0) { wsf[t >> 5] = sf; wsb[t >> 5] = sb; }
    // top-k gather: 12 fg + 12 bg scattered loads from this row (L2 hits)
    if (t < 2 * TOPK) {
        int which = t / TOPK;
        int k     = t % TOPK;
        int idx   = g_idx[(which * BS + b) * TOPK + k];
        tkv[t] = feat[rowoff + (size_t)idx];
    }
    __syncthreads();
    if (t == 0) {
        float SF = 0.0f, SB = 0.0f;
        #pragma unroll
        for (int w = 0; w < 8; w++) { SF += wsf[w]; SB += wsb[w]; }
        float TF = 0.0f, TB = 0.0f;
        #pragma unroll
        for (int k = 0; k < TOPK; k++) { TF += tkv[k]; TB += tkv[TOPK + k]; }
        int cf = g_cnt[b], cb = g_cnt[BS + b];
        float mf = (cf > 0) ? SF / (float)cf : TF / (float)TOPK;
        float mb = (cb > 0) ? SB / (float)cb : TB / (float)TOPK;
        res[b * CCH + c]            = mf;   // fg_proto
        res[BS * CCH + b * CCH + c] = mb;   // bg_proto
    }
}

extern "C" void kernel_launch(void* const* d_in, const int* in_sizes, int n_in,
                              void* d_out, int out_size) {
    const float* feat   = (const float*)d_in[0];   // feature_q (16,256,128,128)
    const float* logits = (const float*)d_in[1];   // out       (16,2,128,128)
    const float* tau    = (const float*)d_in[2];   // tau scalar
    float* res = (float*)d_out;                    // [fg(16*256) | bg(16*256)]

    ssp_phaseA<<<BS, TPB>>>(logits, tau);
    ssp_phaseB<<<dim3(CCH, BS), TPB>>>(feat, res);
}

// round 2
// speedup vs baseline: 5.2891x; 5.2891x over previous
#include <cuda_runtime.h>

#define BS    16
#define CCH   256
#define NPIX  16384
#define TOPK  12
#define TPB   256
#define ACH   8          // phaseA chunks per batch

// Device-global scratch (no allocations allowed anywhere)
__device__ signed char g_mask[BS * NPIX];          // bit0 = fg mask, bit1 = bg mask
__device__ int         g_cntp[2 * BS * ACH];       // per-chunk partial counts [side][b][chunk]
__device__ int         g_idx[2 * BS * TOPK];       // fallback top-12 indices (valid only if cnt==0)

// ---------------------------------------------------------------------------
// Phase A: softmax -> masks + partial counts. grid (ACH, BS), 256 thr.
// Each block handles NPIX/ACH = 2048 pixels (512 float4 per logit channel).
// ---------------------------------------------------------------------------
__global__ void ssp_phaseA(const float* __restrict__ logits,
                           const float* __restrict__ tau_p) {
    int chunk = blockIdx.x, b = blockIdx.y, t = threadIdx.x;
    float tau = tau_p[0];
    float tf  = 1.0f / (1.0f + expf(-tau));
    float tb  = 1.0f - tf;

    const int pix0 = chunk * (NPIX / ACH);
    const float4* o0 = (const float4*)(logits + (size_t)b * 2 * NPIX + pix0);
    const float4* o1 = (const float4*)(logits + (size_t)b * 2 * NPIX + NPIX + pix0);
    char4* mp = (char4*)(g_mask + (size_t)b * NPIX + pix0);

    int lf = 0, lb = 0;
    #pragma unroll
    for (int it = 0; it < (NPIX / ACH / 4) / TPB; ++it) {   // 2 iters
        int i = t + it * TPB;
        float4 a0 = o0[i], a1 = o1[i];
        char4 m;
        {
            float mx = fmaxf(a0.x, a1.x);
            float e0 = expf(a0.x - mx), e1 = expf(a1.x - mx);
            float pf = e1 / (e0 + e1), pb = e0 / (e0 + e1);
            int s = 0; if (pf > tf) { s |= 1; lf++; } if (pb > tb) { s |= 2; lb++; }
            m.x = (signed char)s;
        }
        {
            float mx = fmaxf(a0.y, a1.y);
            float e0 = expf(a0.y - mx), e1 = expf(a1.y - mx);
            float pf = e1 / (e0 + e1), pb = e0 / (e0 + e1);
            int s = 0; if (pf > tf) { s |= 1; lf++; } if (pb > tb) { s |= 2; lb++; }
            m.y = (signed char)s;
        }
        {
            float mx = fmaxf(a0.z, a1.z);
            float e0 = expf(a0.z - mx), e1 = expf(a1.z - mx);
            float pf = e1 / (e0 + e1), pb = e0 / (e0 + e1);
            int s = 0; if (pf > tf) { s |= 1; lf++; } if (pb > tb) { s |= 2; lb++; }
            m.z = (signed char)s;
        }
        {
            float mx = fmaxf(a0.w, a1.w);
            float e0 = expf(a0.w - mx), e1 = expf(a1.w - mx);
            float pf = e1 / (e0 + e1), pb = e0 / (e0 + e1);
            int s = 0; if (pf > tf) { s |= 1; lf++; } if (pb > tb) { s |= 2; lb++; }
            m.w = (signed char)s;
        }
        mp[i] = m;
    }
    // block-reduce counts
    __shared__ int scf[TPB / 32], scb[TPB / 32];
    #pragma unroll
    for (int off = 16; off; off >>= 1) {
        lf += __shfl_down_sync(0xffffffffu, lf, off);
        lb += __shfl_down_sync(0xffffffffu, lb, off);
    }
    if ((t & 31) == 0) { scf[t >> 5] = lf; scb[t >> 5] = lb; }
    __syncthreads();
    if (t == 0) {
        int cf = 0, cb = 0;
        #pragma unroll
        for (int w = 0; w < TPB / 32; w++) { cf += scf[w]; cb += scb[w]; }
        g_cntp[(0 * BS + b) * ACH + chunk] = cf;
        g_cntp[(1 * BS + b) * ACH + chunk] = cb;
    }
}

__device__ __forceinline__ int total_cnt(int side, int b) {
    int c = 0;
    #pragma unroll
    for (int k = 0; k < ACH; k++) c += g_cntp[(side * BS + b) * ACH + k];
    return c;
}

// ---------------------------------------------------------------------------
// Top-k fallback: grid 32 = (b, side). Runs the expensive top-12 ONLY if the
// corresponding count is zero (output doesn't depend on it otherwise).
// Probabilities recomputed from logits on the fly.
// ---------------------------------------------------------------------------
__global__ void ssp_topk(const float* __restrict__ logits) {
    int b = blockIdx.x & (BS - 1);
    int side = blockIdx.x >> 4;            // 0 = fg, 1 = bg
    if (total_cnt(side, b) > 0) return;    // common path: no work

    int t = threadIdx.x;
    __shared__ float sv[TPB];
    __shared__ int   si[TPB];
    __shared__ int   ch[TOPK];
    const float* o0 = logits + (size_t)b * 2 * NPIX;
    const float* o1 = o0 + NPIX;

    for (int k = 0; k < TOPK; k++) {
        float best = -3.402823466e38f;
        int   bidx = NPIX;
        for (int i = t; i < NPIX; i += TPB) {
            bool excl = false;
            #pragma unroll
            for (int j = 0; j < TOPK; j++)
                if (j < k) excl |= (i == ch[j]);
            if (!excl) {
                float a0 = o0[i], a1 = o1[i];
                float mx = fmaxf(a0, a1);
                float e0 = expf(a0 - mx), e1 = expf(a1 - mx);
                float p = (side == 0) ? e1 / (e0 + e1) : e0 / (e0 + e1);
                if (p > best) { best = p; bidx = i; }
            }
        }
        sv[t] = best; si[t] = bidx;
        __syncthreads();
        for (int off = TPB / 2; off > 0; off >>= 1) {
            if (t < off) {
                float v2 = sv[t + off]; int i2 = si[t + off];
                if (v2 > sv[t] || (v2 == sv[t] && i2 < si[t])) { sv[t] = v2; si[t] = i2; }
            }
            __syncthreads();
        }
        if (t == 0) ch[k] = si[0];
        __syncthreads();
    }
    if (t < TOPK) g_idx[(side * BS + b) * TOPK + t] = ch[t];
}

// ---------------------------------------------------------------------------
// Phase B: streaming masked reduction. One block per (b,c) row.
// ---------------------------------------------------------------------------
__global__ void ssp_phaseB(const float* __restrict__ feat,
                           float* __restrict__ res) {
    int c = blockIdx.x, b = blockIdx.y, t = threadIdx.x;
    size_t rowoff = ((size_t)b * CCH + c) * (size_t)NPIX;
    const float4* row = (const float4*)(feat + rowoff);
    const char4*  sp  = (const char4*)(g_mask + (size_t)b * NPIX);

    float sf = 0.0f, sb = 0.0f;
    #pragma unroll
    for (int it = 0; it < NPIX / 4 / TPB; ++it) {   // 16 x LDG.128 (streaming)
        int i = t + it * TPB;
        float4 v = __ldcs(&row[i]);
        char4  m = sp[i];
        sf += (m.x & 1) ? v.x : 0.0f;  sb += (m.x & 2) ? v.x : 0.0f;
        sf += (m.y & 1) ? v.y : 0.0f;  sb += (m.y & 2) ? v.y : 0.0f;
        sf += (m.z & 1) ? v.z : 0.0f;  sb += (m.z & 2) ? v.z : 0.0f;
        sf += (m.w & 1) ? v.w : 0.0f;  sb += (m.w & 2) ? v.w : 0.0f;
    }
    #pragma unroll
    for (int off = 16; off; off >>= 1) {
        sf += __shfl_down_sync(0xffffffffu, sf, off);
        sb += __shfl_down_sync(0xffffffffu, sb, off);
    }
    __shared__ float wsf[8], wsb[8];
    __shared__ float tkv[2 * TOPK];
    __shared__ int   scnt[2];
    if ((t & 31) == 0) { wsf[t >> 5] = sf; wsb[t >> 5] = sb; }
    if (t < 2) scnt[t] = total_cnt(t, b);
    __syncthreads();
    // fallback gather only when the count is zero (indices undefined otherwise)
    if (t < 2 * TOPK) {
        int side = t / TOPK, k = t % TOPK;
        float v = 0.0f;
        if (scnt[side] == 0) {
            int idx = g_idx[(side * BS + b) * TOPK + k];
            v = feat[rowoff + (size_t)idx];
        }
        tkv[t] = v;
    }
    __syncthreads();
    if (t == 0) {
        float SF = 0.0f, SB = 0.0f;
        #pragma unroll
        for (int w = 0; w < 8; w++) { SF += wsf[w]; SB += wsb[w]; }
        float TF = 0.0f, TB = 0.0f;
        #pragma unroll
        for (int k = 0; k < TOPK; k++) { TF += tkv[k]; TB += tkv[TOPK + k]; }
        int cf = scnt[0], cb = scnt[1];
        float mf = (cf > 0) ? SF / (float)cf : TF / (float)TOPK;
        float mb = (cb > 0) ? SB / (float)cb : TB / (float)TOPK;
        res[b * CCH + c]            = mf;   // fg_proto
        res[BS * CCH + b * CCH + c] = mb;   // bg_proto
    }
}

extern "C" void kernel_launch(void* const* d_in, const int* in_sizes, int n_in,
                              void* d_out, int out_size) {
    const float* feat   = (const float*)d_in[0];   // feature_q (16,256,128,128)
    const float* logits = (const float*)d_in[1];   // out       (16,2,128,128)
    const float* tau    = (const float*)d_in[2];   // tau scalar
    float* res = (float*)d_out;                    // [fg(16*256) | bg(16*256)]

    ssp_phaseA<<<dim3(ACH, BS), TPB>>>(logits, tau);
    ssp_topk<<<2 * BS, TPB>>>(logits);
    ssp_phaseB<<<dim3(CCH, BS), TPB>>>(feat, res);
}